// round 1
// baseline (speedup 1.0000x reference)
#include <cuda_runtime.h>
#include <cuda_bf16.h>

#define S_LEN 2048
#define E_DIM 1024
#define N_H   16
#define N_KVH 8
#define HD    64
#define N_REP 2
#define KV_E  (N_KVH * HD)   // 512

// Scratch (device globals — no allocation allowed)
__device__ float g_q [S_LEN * E_DIM];   // 8 MB
__device__ float g_k [S_LEN * KV_E];    // 4 MB
__device__ float g_v [S_LEN * KV_E];    // 4 MB
__device__ float g_ao[S_LEN * E_DIM];   // 8 MB (attention output pre-projection)

// ---------------------------------------------------------------------------
// Generic NT SGEMM: C[m,n] = sum_k A[m,k] * B[n,k]  (+ bias[n])
// Per-head offsets: A += h*saH, B += (h/bDiv)*sbH, C += h*scH
// BM=BN=64, BK=16, 256 threads, 4x4 microtile. All dims assumed multiples.
// ---------------------------------------------------------------------------
__global__ __launch_bounds__(256)
void gemm_nt(int K,
             const float* __restrict__ A, int lda, int saH,
             const float* __restrict__ B, int ldb, int sbH, int bDiv,
             float* __restrict__ C, int ldc, long long scH,
             const float* __restrict__ bias)
{
    const int h = blockIdx.z;
    A += (size_t)h * saH;
    B += (size_t)(h / bDiv) * sbH;
    C += (size_t)h * scH;

    __shared__ float As[64][17];
    __shared__ float Bs[64][17];

    const int bm = blockIdx.y * 64;
    const int bn = blockIdx.x * 64;
    const int tid = threadIdx.x;
    const int tx = tid & 15;   // n-dir
    const int ty = tid >> 4;   // m-dir

    float acc[4][4] = {};

    const int lk = tid & 15;
    const int lr = tid >> 4;

    for (int k0 = 0; k0 < K; k0 += 16) {
        #pragma unroll
        for (int i = 0; i < 4; i++) {
            int r = lr + i * 16;
            As[r][lk] = A[(size_t)(bm + r) * lda + k0 + lk];
            Bs[r][lk] = B[(size_t)(bn + r) * ldb + k0 + lk];
        }
        __syncthreads();
        #pragma unroll
        for (int kk = 0; kk < 16; kk++) {
            float a[4], b[4];
            #pragma unroll
            for (int i = 0; i < 4; i++) a[i] = As[ty * 4 + i][kk];
            #pragma unroll
            for (int j = 0; j < 4; j++) b[j] = Bs[tx * 4 + j][kk];
            #pragma unroll
            for (int i = 0; i < 4; i++)
                #pragma unroll
                for (int j = 0; j < 4; j++)
                    acc[i][j] += a[i] * b[j];
        }
        __syncthreads();
    }

    #pragma unroll
    for (int i = 0; i < 4; i++) {
        int r = bm + ty * 4 + i;
        #pragma unroll
        for (int j = 0; j < 4; j++) {
            int c = bn + tx * 4 + j;
            float v = acc[i][j];
            if (bias) v += bias[c];
            C[(size_t)r * ldc + c] = v;
        }
    }
}

// ---------------------------------------------------------------------------
// RoPE (in-place on Q and K). One thread per complex pair.
// ---------------------------------------------------------------------------
__global__ __launch_bounds__(256)
void rope_kernel(float* __restrict__ q, float* __restrict__ k,
                 const float* __restrict__ cosv, const float* __restrict__ sinv)
{
    int idx = blockIdx.x * blockDim.x + threadIdx.x;
    const int totq = S_LEN * N_H * (HD / 2);
    if (idx < totq) {
        int i = idx & 31;
        int h = (idx >> 5) & (N_H - 1);
        int s = idx >> 9;
        float c  = cosv[s * 32 + i];
        float sn = sinv[s * 32 + i];
        float* p = q + ((size_t)s * N_H + h) * HD + 2 * i;
        float xr = p[0], xi = p[1];
        p[0] = xr * c - xi * sn;
        p[1] = xr * sn + xi * c;
    } else {
        idx -= totq;
        if (idx < S_LEN * N_KVH * (HD / 2)) {
            int i = idx & 31;
            int h = (idx >> 5) & (N_KVH - 1);
            int s = idx >> 8;
            float c  = cosv[s * 32 + i];
            float sn = sinv[s * 32 + i];
            float* p = k + ((size_t)s * N_KVH + h) * HD + 2 * i;
            float xr = p[0], xi = p[1];
            p[0] = xr * c - xi * sn;
            p[1] = xr * sn + xi * c;
        }
    }
}

// ---------------------------------------------------------------------------
// Softmax over key dim for one (h, q) row. Reads raw dots (already in w),
// applies 1/sqrt(D), clamps, adds bias matrix, stable softmax, writes back.
// Row length 2048, 256 threads x 8 elements in registers.
// ---------------------------------------------------------------------------
__global__ __launch_bounds__(256)
void softmax_kernel(float* __restrict__ w, const float* __restrict__ bias)
{
    const int q = blockIdx.x;
    const int h = blockIdx.y;
    float* row       = w    + ((size_t)h * S_LEN + q) * S_LEN;
    const float* brw = bias + ((size_t)h * S_LEN + q) * S_LEN;

    const float scale = 0.125f;  // 1/sqrt(64)
    const int t = threadIdx.x;

    float vals[8];
    float m = -1e30f;
    #pragma unroll
    for (int i = 0; i < 8; i++) {
        int c = t + i * 256;
        float z = row[c] * scale;
        z = fminf(fmaxf(z, -50000.0f), 50000.0f) + brw[c];
        vals[i] = z;
        m = fmaxf(m, z);
    }

    __shared__ float red[8];
    #pragma unroll
    for (int o = 16; o; o >>= 1) m = fmaxf(m, __shfl_xor_sync(~0u, m, o));
    if ((t & 31) == 0) red[t >> 5] = m;
    __syncthreads();
    float bm = red[0];
    #pragma unroll
    for (int i = 1; i < 8; i++) bm = fmaxf(bm, red[i]);
    __syncthreads();

    float sum = 0.0f;
    #pragma unroll
    for (int i = 0; i < 8; i++) {
        vals[i] = __expf(vals[i] - bm);
        sum += vals[i];
    }
    #pragma unroll
    for (int o = 16; o; o >>= 1) sum += __shfl_xor_sync(~0u, sum, o);
    if ((t & 31) == 0) red[t >> 5] = sum;
    __syncthreads();
    float bs = 0.0f;
    #pragma unroll
    for (int i = 0; i < 8; i++) bs += red[i];
    float inv = 1.0f / bs;

    #pragma unroll
    for (int i = 0; i < 8; i++) row[t + i * 256] = vals[i] * inv;
}

// ---------------------------------------------------------------------------
// PV GEMM (NN): g_ao[q, h*64+d] = sum_k W[h,q,k] * V[k, (h/2)*64 + d]
// BM=64, BN=64 (full D tile), BK=16.
// ---------------------------------------------------------------------------
__global__ __launch_bounds__(256)
void gemm_pv(const float* __restrict__ W, const float* __restrict__ V,
             float* __restrict__ C)
{
    const int h = blockIdx.z;
    const float* A = W + (size_t)h * S_LEN * S_LEN;
    const float* B = V + (h / N_REP) * HD;     // ldb = KV_E
    float* Co = C + h * HD;                    // ldc = E_DIM

    __shared__ float As[64][17];
    __shared__ float Bs[16][64];

    const int bm = blockIdx.y * 64;
    const int tid = threadIdx.x;
    const int tx = tid & 15;
    const int ty = tid >> 4;

    float acc[4][4] = {};

    const int lk = tid & 15;
    const int lr = tid >> 4;
    const int ln  = tid & 63;
    const int lkk = tid >> 6;

    for (int k0 = 0; k0 < S_LEN; k0 += 16) {
        #pragma unroll
        for (int i = 0; i < 4; i++) {
            int r = lr + i * 16;
            As[r][lk] = A[(size_t)(bm + r) * S_LEN + k0 + lk];
        }
        #pragma unroll
        for (int i = 0; i < 4; i++) {
            int kr = lkk + i * 4;
            Bs[kr][ln] = B[(size_t)(k0 + kr) * KV_E + ln];
        }
        __syncthreads();
        #pragma unroll
        for (int kk = 0; kk < 16; kk++) {
            float a[4], b[4];
            #pragma unroll
            for (int i = 0; i < 4; i++) a[i] = As[ty * 4 + i][kk];
            #pragma unroll
            for (int j = 0; j < 4; j++) b[j] = Bs[kk][tx * 4 + j];
            #pragma unroll
            for (int i = 0; i < 4; i++)
                #pragma unroll
                for (int j = 0; j < 4; j++)
                    acc[i][j] += a[i] * b[j];
        }
        __syncthreads();
    }

    #pragma unroll
    for (int i = 0; i < 4; i++) {
        int r = bm + ty * 4 + i;
        #pragma unroll
        for (int j = 0; j < 4; j++) {
            int c = tx * 4 + j;
            Co[(size_t)r * E_DIM + c] = acc[i][j];
        }
    }
}

// ---------------------------------------------------------------------------
extern "C" void kernel_launch(void* const* d_in, const int* in_sizes, int n_in,
                              void* d_out, int out_size)
{
    const float* x         = (const float*)d_in[0];
    const float* attn_bias = (const float*)d_in[1];
    const float* fcos      = (const float*)d_in[2];
    const float* fsin      = (const float*)d_in[3];
    const float* wq_w      = (const float*)d_in[4];
    const float* wk_w      = (const float*)d_in[5];
    const float* wk_b      = (const float*)d_in[6];
    const float* wv_w      = (const float*)d_in[7];
    const float* wv_b      = (const float*)d_in[8];
    const float* wo_w      = (const float*)d_in[9];
    const float* wo_b      = (const float*)d_in[10];

    float* out   = (float*)d_out;                       // (S, E)
    float* attnw = (float*)d_out + (size_t)S_LEN * E_DIM; // (H, S, S)

    float *q, *k, *v, *ao;
    cudaGetSymbolAddress((void**)&q,  g_q);
    cudaGetSymbolAddress((void**)&k,  g_k);
    cudaGetSymbolAddress((void**)&v,  g_v);
    cudaGetSymbolAddress((void**)&ao, g_ao);

    // 1-3. QKV projections
    gemm_nt<<<dim3(E_DIM/64, S_LEN/64, 1), 256>>>(E_DIM,
        x, E_DIM, 0, wq_w, E_DIM, 0, 1, q, E_DIM, 0, nullptr);
    gemm_nt<<<dim3(KV_E/64, S_LEN/64, 1), 256>>>(E_DIM,
        x, E_DIM, 0, wk_w, E_DIM, 0, 1, k, KV_E, 0, wk_b);
    gemm_nt<<<dim3(KV_E/64, S_LEN/64, 1), 256>>>(E_DIM,
        x, E_DIM, 0, wv_w, E_DIM, 0, 1, v, KV_E, 0, wv_b);

    // 4. RoPE on Q and K
    {
        int tot = S_LEN * N_H * 32 + S_LEN * N_KVH * 32;
        rope_kernel<<<(tot + 255) / 256, 256>>>(q, k, fcos, fsin);
    }

    // 5. Scores (raw dots) into attn_weights region
    gemm_nt<<<dim3(S_LEN/64, S_LEN/64, N_H), 256>>>(HD,
        q, E_DIM, HD,
        k, KV_E, HD, N_REP,
        attnw, S_LEN, (long long)S_LEN * S_LEN, nullptr);

    // 6. Softmax (scale, clamp, +bias) in place
    softmax_kernel<<<dim3(S_LEN, N_H), 256>>>(attnw, attn_bias);

    // 7. PV
    gemm_pv<<<dim3(1, S_LEN/64, N_H), 256>>>(attnw, v, ao);

    // 8. Output projection
    gemm_nt<<<dim3(E_DIM/64, S_LEN/64, 1), 256>>>(E_DIM,
        ao, E_DIM, 0, wo_w, E_DIM, 0, 1, out, E_DIM, 0, wo_b);
}